// round 16
// baseline (speedup 1.0000x reference)
#include <cuda_runtime.h>
#include <cstdint>

// out[b] = 0.5 * mean(sigmoid(conv2d_valid(data, w4x4) + b)) for all b (broadcast).
// Quantum term is exactly 0 (RX(pi) = -i*X and the CX chain are basis perms /
// global phases on the uniform H^n|0> state => qexp[b] = 0 for all b).
// sigmoid(x) = 0.5 + 0.5*tanh(x/2): fold 0.5 into weights/bias, accumulate tanh,
// final = 0.25 + 0.25*mean(tanh). Conv on packed fma.rn.f32x2 (FFMA2).
// Images staged in smem (coalesced, dedup'd loads); window served by LDS.128.

#define IMG 64
#define OUT 61
#define NPOS (OUT * OUT)          // 3721
#define NBATCH 256
#define NCTA 128                  // one balanced wave, 2 images per CTA
#define THREADS 512
#define NBUCKET 16
#define BSTRIDE 32                // floats -> 128B apart

__device__ float        g_part[NBUCKET * BSTRIDE];   // zero-initialized
__device__ unsigned int g_count = 0u;

__device__ __forceinline__ float tanh_fast(float x) {
    float r;
    asm("tanh.approx.f32 %0, %1;" : "=f"(r) : "f"(x));
    return r;
}
__device__ __forceinline__ uint64_t pack2(float lo, float hi) {
    uint64_t d;
    asm("mov.b64 %0, {%1, %2};" : "=l"(d) : "f"(lo), "f"(hi));
    return d;
}
__device__ __forceinline__ void unpack2(float& lo, float& hi, uint64_t d) {
    asm("mov.b64 {%0, %1}, %2;" : "=f"(lo), "=f"(hi) : "l"(d));
}
__device__ __forceinline__ uint64_t fma2(uint64_t a, uint64_t b, uint64_t c) {
    uint64_t d;
    asm("fma.rn.f32x2 %0, %1, %2, %3;" : "=l"(d) : "l"(a), "l"(b), "l"(c));
    return d;
}

__global__ __launch_bounds__(THREADS)
void conv_sigmoid_mean_kernel(const float* __restrict__ data,
                              const float* __restrict__ w,
                              const float* __restrict__ b,
                              float* __restrict__ out) {
    // 2 images (2*1024 float4) + 1 float4 pad for the clamped-row-63 r+1 read
    __shared__ float4 tile[2 * 1024 + 1];
    __shared__ float  warp_sums[THREADS / 32];
    __shared__ int    is_last;
    __shared__ float  tot;

    const int t     = threadIdx.x;
    const int local = t & 255;                      // 256 threads per image
    const int half  = t >> 8;                       // which of the 2 images
    const int blk   = local >> 4;                   // 0..15 row-blocks (4 rows)
    const int chunk = local & 15;                   // 0..15 x-chunks (4 cols)
    const int x0    = chunk * 4;                    // 0,4,...,60
    const int y0    = blk * 4;                      // blk 15 -> only row 60 valid

    // Stage both images: 2048 float4, 4 per thread, fully coalesced
    const float4* src4 = reinterpret_cast<const float4*>(data)
                       + (size_t)(blockIdx.x << 1) * 1024;
    #pragma unroll
    for (int i = 0; i < 4; i++) {
        tile[t + i * THREADS] = __ldg(src4 + t + i * THREADS);
    }

    // Pre-scaled weights/bias (uniform loads, overlap the staging)
    float sw[16];
    #pragma unroll
    for (int i = 0; i < 16; i++) sw[i] = 0.5f * __ldg(w + i);
    const float    bias05 = 0.5f * __ldg(b);
    const uint64_t bias2  = pack2(bias05, bias05);

    __syncthreads();

    // Read the 7-row x 8-col window from smem: 14 LDS.128
    const float4* img4 = tile + half * 1024 + (x0 >> 2);
    float4 R0[7], R1[7];
    #pragma unroll
    for (int s = 0; s < 7; s++) {
        int ry = y0 + s;
        ry = (ry > 63) ? 63 : ry;                   // clamp; garbage rows masked
        const float4* r = img4 + ry * (IMG / 4);
        R0[s] = r[0];
        R1[s] = r[1];   // chunk 15: next-row garbage (or pad), feeds masked cols only
    }

    // 8 packed accumulators: output rows k=0..3, column pairs q=0..1
    uint64_t acc2[8];
    #pragma unroll
    for (int i = 0; i < 8; i++) acc2[i] = bias2;

    #pragma unroll
    for (int r = 0; r < 7; r++) {
        const float4 v0 = R0[r], v1 = R1[r];
        const float win[8] = {v0.x, v0.y, v0.z, v0.w, v1.x, v1.y, v1.z, v1.w};
        uint64_t P[6];
        #pragma unroll
        for (int a = 0; a < 6; a++) P[a] = pack2(win[a], win[a + 1]);

        #pragma unroll
        for (int k = 0; k < 4; k++) {
            if (r - k >= 0 && r - k <= 3) {
                const int i = r - k;                // weight row
                #pragma unroll
                for (int j = 0; j < 4; j++) {
                    const uint64_t w2 = pack2(sw[i * 4 + j], sw[i * 4 + j]);
                    acc2[k * 2 + 0] = fma2(P[j],     w2, acc2[k * 2 + 0]);
                    acc2[k * 2 + 1] = fma2(P[j + 2], w2, acc2[k * 2 + 1]);
                }
            }
        }
    }

    float lsum = 0.0f;
    #pragma unroll
    for (int k = 0; k < 4; k++) {
        if (y0 + k < OUT) {
            float a0, a1, a2, a3;
            unpack2(a0, a1, acc2[k * 2 + 0]);
            unpack2(a2, a3, acc2[k * 2 + 1]);
            lsum += tanh_fast(a0);                       // x0+0 always < OUT
            if (x0 + 1 < OUT) lsum += tanh_fast(a1);
            if (x0 + 2 < OUT) lsum += tanh_fast(a2);
            if (x0 + 3 < OUT) lsum += tanh_fast(a3);
        }
    }

    // warp reduce
    #pragma unroll
    for (int off = 16; off > 0; off >>= 1)
        lsum += __shfl_xor_sync(0xFFFFFFFFu, lsum, off);

    const int wid = t >> 5;
    const int lid = t & 31;
    if (lid == 0) warp_sums[wid] = lsum;
    __syncthreads();

    if (t == 0) {
        float s = 0.0f;
        #pragma unroll
        for (int i = 0; i < THREADS / 32; i++) s += warp_sums[i];
        atomicAdd(&g_part[(blockIdx.x & (NBUCKET - 1)) * BSTRIDE], s);
        __threadfence();
        unsigned int prev = atomicAdd(&g_count, 1u);
        is_last = (prev == (unsigned)(NCTA - 1)) ? 1 : 0;
        if (is_last) {
            // all prior g_part adds visible (each CTA fenced before counting)
            float tsum = 0.0f;
            #pragma unroll
            for (int i = 0; i < NBUCKET; i++) tsum += g_part[i * BSTRIDE];
            tot = 0.25f + 0.25f * tsum / (float)(NBATCH * NPOS);
        }
    }
    __syncthreads();

    if (is_last) {
        if (t < NBATCH) out[t] = tot;
        // self-clean for the next graph replay
        if (t < NBUCKET) g_part[t * BSTRIDE] = 0.0f;
        if (t == 0)      g_count = 0u;
        __threadfence();
    }
}

extern "C" void kernel_launch(void* const* d_in, const int* in_sizes, int n_in,
                              void* d_out, int out_size) {
    const float* data = (const float*)d_in[0];   // 256*1*64*64
    const float* w    = (const float*)d_in[1];   // 1*1*4*4
    const float* b    = (const float*)d_in[2];   // 1
    float* out = (float*)d_out;                  // 256 floats

    conv_sigmoid_mean_kernel<<<NCTA, THREADS>>>(data, w, b, out);
}